// round 14
// baseline (speedup 1.0000x reference)
#include <cuda_runtime.h>
#include <cuda_bf16.h>
#include <cstdint>
#include <math.h>

#define Bsz   8
#define C     384
#define NHEAD 12
#define HD    32
#define FF    1536
#define MROWS 32768   // B * H * W = 8*64*64

typedef __nv_bfloat16 bf16;

// ---------------- scratch (device globals; no allocation) ----------------
__device__ float g_ada[Bsz * 2304];
__device__ bf16  g_qkvb[(size_t)MROWS * 1152];     // bf16 QKV
__device__ bf16  g_ab[(size_t)MROWS * C];          // bf16 activations (LN out / attn out)
__device__ bf16  g_fb[(size_t)MROWS * FF];         // bf16 FF1 output
#define WTOT 3538944
__device__ bf16  g_wb[WTOT];
#define W_QKV 0
#define W_PROJ 884736
#define W_FF1 1179648
#define W_FF2 2359296

// epilogue kinds
#define OUT_BF16      0   // plain bf16 store (QKV)
#define OUT_GELU_BF16 1   // GELU -> bf16 store (FF1)
#define OUT_RESID_SA  2   // x[drow] += g_sa * v (proj, window/shift un-scatter)
#define OUT_RESID_FF  3   // x[row] += g_ff * v (FF2)

// ---------------- copy x -> out ----------------
__global__ void copy_kernel(float* __restrict__ dst, const float* __restrict__ src, int n) {
    int i = blockIdx.x * blockDim.x + threadIdx.x;
    if (i < n) dst[i] = src[i];
}

// ---------------- fp32 -> bf16 ----------------
__global__ void cvt_bf16(const float* __restrict__ src, bf16* __restrict__ dst, int n) {
    int i = blockIdx.x * blockDim.x + threadIdx.x;
    if (i < n) dst[i] = __float2bfloat16(src[i]);
}

// ---------------- adaLN ----------------
__global__ void ada_kernel(const float* __restrict__ emb, const float* __restrict__ ada_w,
                           const float* __restrict__ ada_b, float* __restrict__ ada_out) {
    int b = blockIdx.y;
    int j = blockIdx.x * blockDim.x + threadIdx.x;
    __shared__ float se[C];
    for (int k = threadIdx.x; k < C; k += blockDim.x) {
        float e = emb[b * C + k];
        se[k] = e / (1.0f + __expf(-e));
    }
    __syncthreads();
    const float* wrow = ada_w + (size_t)j * C;
    float s = ada_b[j];
#pragma unroll 4
    for (int k = 0; k < C; k++) s += se[k] * wrow[k];
    ada_out[b * 2304 + j] = s;
}

// ---------------- LayerNorm + modulate -> bf16 (+ optional window/shift gather) ----------------
__global__ void ln_mod_kernel(const float* __restrict__ x, const float* __restrict__ ada,
                              bf16* __restrict__ out, int shift, int windowed,
                              int sc_off, int sh_off) {
    int wrow = blockIdx.x;
    int tid = threadIdx.x;
    int b, srcrow;
    if (windowed) {
        int win = wrow >> 6, n = wrow & 63;
        b = win >> 6;
        int widx = win & 63;
        int wh = widx >> 3, wwi = widx & 7, ii = n >> 3, jj = n & 7;
        int r = (wh * 8 + ii + shift) & 63;
        int cc = (wwi * 8 + jj + shift) & 63;
        srcrow = b * 4096 + r * 64 + cc;
    } else {
        b = wrow >> 12;
        srcrow = wrow;
    }
    const float* xr = x + (size_t)srcrow * C;
    float v0 = xr[tid], v1 = xr[tid + 128], v2 = xr[tid + 256];
    float s = v0 + v1 + v2;
    float q = v0 * v0 + v1 * v1 + v2 * v2;
#pragma unroll
    for (int o = 16; o > 0; o >>= 1) {
        s += __shfl_down_sync(0xffffffffu, s, o);
        q += __shfl_down_sync(0xffffffffu, q, o);
    }
    __shared__ float rs[4], rq[4], mv[2];
    int wid = tid >> 5, lane = tid & 31;
    if (lane == 0) { rs[wid] = s; rq[wid] = q; }
    __syncthreads();
    if (tid == 0) {
        float S = rs[0] + rs[1] + rs[2] + rs[3];
        float Q = rq[0] + rq[1] + rq[2] + rq[3];
        float mean = S * (1.0f / C);
        float var = Q * (1.0f / C) - mean * mean;
        mv[0] = mean;
        mv[1] = rsqrtf(var + 1e-6f);
    }
    __syncthreads();
    float mean = mv[0], rstd = mv[1];
    const float* sc = ada + b * 2304 + sc_off;
    const float* sh = ada + b * 2304 + sh_off;
    bf16* orow = out + (size_t)wrow * C;
    orow[tid]       = __float2bfloat16((v0 - mean) * rstd * (1.0f + sc[tid])       + sh[tid]);
    orow[tid + 128] = __float2bfloat16((v1 - mean) * rstd * (1.0f + sc[tid + 128]) + sh[tid + 128]);
    orow[tid + 256] = __float2bfloat16((v2 - mean) * rstd * (1.0f + sc[tid + 256]) + sh[tid + 256]);
}

// ================= bf16 tensor-core GEMM (mma.m16n8k16 + ldmatrix) =================
// BM=256, BN=128, BK=64; 512 threads / 16 warps (4x4), warp tile 64x32;
// 3-stage cp.async; epilogue fused per outKind (see defines).
#define ROWB 144                       // bytes per smem row (72 bf16)
#define A_BYTES (256 * ROWB)
#define STG_BYTES (A_BYTES + 128 * ROWB)
#define GEMM_SMEM (3 * STG_BYTES)

__device__ __forceinline__ void cpasync16(uint32_t dst, const void* src) {
    asm volatile("cp.async.cg.shared.global [%0], [%1], 16;" :: "r"(dst), "l"(src));
}
__device__ __forceinline__ void cp_commit() { asm volatile("cp.async.commit_group;"); }
__device__ __forceinline__ void cp_wait0() { asm volatile("cp.async.wait_group 0;"); }
__device__ __forceinline__ void cp_wait1() { asm volatile("cp.async.wait_group 1;"); }

__device__ __forceinline__ void ldsm4(uint32_t& r0, uint32_t& r1, uint32_t& r2, uint32_t& r3,
                                      uint32_t addr) {
    asm volatile("ldmatrix.sync.aligned.m8n8.x4.shared.b16 {%0,%1,%2,%3}, [%4];"
                 : "=r"(r0), "=r"(r1), "=r"(r2), "=r"(r3) : "r"(addr));
}

__device__ __forceinline__ void mma_bf16(float* d, uint32_t a0, uint32_t a1, uint32_t a2,
                                         uint32_t a3, uint32_t b0, uint32_t b1) {
    asm volatile(
        "mma.sync.aligned.m16n8k16.row.col.f32.bf16.bf16.f32 "
        "{%0,%1,%2,%3}, {%4,%5,%6,%7}, {%8,%9}, {%0,%1,%2,%3};"
        : "+f"(d[0]), "+f"(d[1]), "+f"(d[2]), "+f"(d[3])
        : "r"(a0), "r"(a1), "r"(a2), "r"(a3), "r"(b0), "r"(b1));
}

__device__ __forceinline__ void g_load_stage(uint32_t sbase, const bf16* A, const bf16* W,
                                             int K, int kt, int bm, int bn, int tid) {
    int k0 = kt * 64;
#pragma unroll
    for (int j = 0; j < 6; j++) {
        int c = tid + j * 512;
        if (c < 2048) {
            int row = c >> 3, q = c & 7;
            cpasync16(sbase + row * ROWB + q * 16,
                      A + (size_t)(bm + row) * K + k0 + q * 8);
        } else {
            int c2 = c - 2048;
            int row = c2 >> 3, q = c2 & 7;
            cpasync16(sbase + A_BYTES + row * ROWB + q * 16,
                      W + (size_t)(bn + row) * K + k0 + q * 8);
        }
    }
}

__global__ __launch_bounds__(512, 1) void gemm_bf16(const bf16* __restrict__ A,
                                                    const bf16* __restrict__ W,
                                                    const float* __restrict__ bias,
                                                    bf16* __restrict__ Ob,
                                                    float* __restrict__ xres,
                                                    const float* __restrict__ ada,
                                                    int N, int K, int outKind, int shift) {
    extern __shared__ char smem[];

    int tid = threadIdx.x;
    int warp = tid >> 5, lane = tid & 31;
    int grp = lane >> 2, qid = lane & 3;
    int wm = warp & 3, wn = warp >> 2;        // 4 x 4 warp grid
    int m_w = wm * 64, n_w = wn * 32;

    // CTA swizzle for L2 locality
    int NB = gridDim.x, MB = gridDim.y;
    int lin = blockIdx.y * NB + blockIdx.x;
    const int GM = 8;
    int gsz = GM * NB;
    int g = lin / gsz, rr = lin - g * gsz;
    int gm = min(GM, MB - g * GM);
    int mb = g * GM + rr % gm;
    int nb = rr / gm;
    int bm = mb * 256, bn = nb * 128;

    uint32_t sb0 = (uint32_t)__cvta_generic_to_shared(smem);

    int r8 = lane & 7, mat = lane >> 3;
    uint32_t aoff = (uint32_t)((m_w + r8 + (mat & 1) * 8) * ROWB + (mat >> 1) * 16);
    uint32_t boff = (uint32_t)((n_w + 8 * (mat >> 1) + r8) * ROWB + (mat & 1) * 16);

    float acc[4][4][4];
#pragma unroll
    for (int i = 0; i < 4; i++)
#pragma unroll
        for (int j = 0; j < 4; j++)
#pragma unroll
            for (int r = 0; r < 4; r++) acc[i][j][r] = 0.0f;

    int nk = K / 64;
    g_load_stage(sb0, A, W, K, 0, bm, bn, tid); cp_commit();
    if (nk > 1) { g_load_stage(sb0 + STG_BYTES, A, W, K, 1, bm, bn, tid); cp_commit(); }

    for (int kt = 0; kt < nk; kt++) {
        if (kt + 1 < nk) cp_wait1(); else cp_wait0();
        __syncthreads();
        if (kt + 2 < nk) {
            g_load_stage(sb0 + ((kt + 2) % 3) * STG_BYTES, A, W, K, kt + 2, bm, bn, tid);
            cp_commit();
        }
        uint32_t sA = sb0 + (kt % 3) * STG_BYTES;
        uint32_t sB = sA + A_BYTES;
#pragma unroll
        for (int ks = 0; ks < 4; ks++) {
            uint32_t ka = ks * 32;
            uint32_t af[4][4], bfr[2][4];
#pragma unroll
            for (int i = 0; i < 4; i++)
                ldsm4(af[i][0], af[i][1], af[i][2], af[i][3], sA + aoff + i * (16 * ROWB) + ka);
#pragma unroll
            for (int jp = 0; jp < 2; jp++)
                ldsm4(bfr[jp][0], bfr[jp][1], bfr[jp][2], bfr[jp][3],
                      sB + boff + jp * (16 * ROWB) + ka);
#pragma unroll
            for (int i = 0; i < 4; i++)
#pragma unroll
                for (int j = 0; j < 4; j++) {
                    int jp = j >> 1, jl = j & 1;
                    mma_bf16(acc[i][j], af[i][0], af[i][1], af[i][2], af[i][3],
                             bfr[jp][2 * jl], bfr[jp][2 * jl + 1]);
                }
        }
    }

    // fused epilogue
#pragma unroll
    for (int i = 0; i < 4; i++) {
#pragma unroll
        for (int j = 0; j < 4; j++) {
            int col = bn + n_w + 8 * j + 2 * qid;
            float b0 = __ldg(&bias[col]), b1 = __ldg(&bias[col + 1]);
#pragma unroll
            for (int h = 0; h < 2; h++) {
                int row = bm + m_w + 16 * i + grp + 8 * h;
                float v0 = acc[i][j][2 * h] + b0;
                float v1 = acc[i][j][2 * h + 1] + b1;
                if (outKind == OUT_BF16) {
                    *(__nv_bfloat162*)&Ob[(size_t)row * N + col] = __floats2bfloat162_rn(v0, v1);
                } else if (outKind == OUT_GELU_BF16) {
                    v0 = 0.5f * v0 * (1.0f + erff(v0 * 0.70710678118654752f));
                    v1 = 0.5f * v1 * (1.0f + erff(v1 * 0.70710678118654752f));
                    *(__nv_bfloat162*)&Ob[(size_t)row * N + col] = __floats2bfloat162_rn(v0, v1);
                } else if (outKind == OUT_RESID_SA) {
                    int win = row >> 6, n = row & 63;
                    int b = win >> 6, widx = win & 63;
                    int wh = widx >> 3, wwi = widx & 7, ii = n >> 3, jj = n & 7;
                    int r = (wh * 8 + ii + shift) & 63;
                    int cc = (wwi * 8 + jj + shift) & 63;
                    size_t drow = (size_t)b * 4096 + r * 64 + cc;
                    float2 gg = *(const float2*)&ada[b * 2304 + 768 + col];
                    float2* xp = (float2*)&xres[drow * C + col];
                    float2 xv = *xp;
                    xv.x += gg.x * v0; xv.y += gg.y * v1;
                    *xp = xv;
                } else { // OUT_RESID_FF
                    int b = row >> 12;
                    float2 gg = *(const float2*)&ada[b * 2304 + 1920 + col];
                    float2* xp = (float2*)&xres[(size_t)row * C + col];
                    float2 xv = *xp;
                    xv.x += gg.x * v0; xv.y += gg.y * v1;
                    *xp = xv;
                }
            }
        }
    }
}

// ---------------- window attention: bf16 in, two-pass online softmax, bf16 out ----------------
__device__ __forceinline__ int regid(int r) { return r < 56 ? 0 : (r < 60 ? 1 : 2); }

__global__ __launch_bounds__(64, 8) void attn_kernel(const bf16* __restrict__ qkv,
                                                     const float* __restrict__ bias_table,
                                                     bf16* __restrict__ out, int shift) {
    int win = blockIdx.x;
    int head = blockIdx.y;
    int n = threadIdx.x;
    __shared__ float4 ks4[64][8];
    __shared__ float4 vs4[64][8];
    __shared__ float bias_s[225];
    __shared__ int lab_s[64];

    size_t base = (size_t)win * 64 * 1152 + head * HD;
    // fill K/V smem: 64 rows x 32 bf16 each, 4 x 16B chunks per row
#pragma unroll
    for (int i = 0; i < 8; i++) {
        int idx = n + i * 64;          // 0..511
        int m = (idx >> 2) & 63, q = idx & 3;
        const __nv_bfloat162* src = (idx < 256)
            ? (const __nv_bfloat162*)&qkv[base + (size_t)m * 1152 + 384 + q * 8]
            : (const __nv_bfloat162*)&qkv[base + (size_t)m * 1152 + 768 + q * 8];
        float2 f0 = __bfloat1622float2(src[0]);
        float2 f1 = __bfloat1622float2(src[1]);
        float2 f2 = __bfloat1622float2(src[2]);
        float2 f3 = __bfloat1622float2(src[3]);
        float4* dst = (idx < 256) ? &ks4[m][q * 2] : &vs4[m][q * 2];
        dst[0] = make_float4(f0.x, f0.y, f1.x, f1.y);
        dst[1] = make_float4(f2.x, f2.y, f3.x, f3.y);
    }
    float4 q4[8];
#pragma unroll
    for (int q = 0; q < 4; q++) {
        const __nv_bfloat162* src = (const __nv_bfloat162*)&qkv[base + (size_t)n * 1152 + q * 8];
        float2 f0 = __bfloat1622float2(src[0]);
        float2 f1 = __bfloat1622float2(src[1]);
        float2 f2 = __bfloat1622float2(src[2]);
        float2 f3 = __bfloat1622float2(src[3]);
        q4[q * 2]     = make_float4(f0.x, f0.y, f1.x, f1.y);
        q4[q * 2 + 1] = make_float4(f2.x, f2.y, f3.x, f3.y);
    }
    for (int i = n; i < 225; i += 64) bias_s[i] = bias_table[i * NHEAD + head];

    int widx = win & 63;
    int wh = widx >> 3, wwi = widx & 7;
    {
        int ii = n >> 3, jj = n & 7;
        lab_s[n] = regid(wh * 8 + ii) * 3 + regid(wwi * 8 + jj);
    }
    __syncthreads();

    int ni = n >> 3, nj = n & 7;
    int labn = lab_s[n];

    float mx = -1e30f, sm = 0.0f;
#pragma unroll 4
    for (int m = 0; m < 64; m++) {
        float acc = 0.0f;
#pragma unroll
        for (int dq = 0; dq < 8; dq++) {
            float4 k4 = ks4[m][dq];
            acc += q4[dq].x * k4.x + q4[dq].y * k4.y + q4[dq].z * k4.z + q4[dq].w * k4.w;
        }
        int mi = m >> 3, mj = m & 7;
        acc = acc * 0.17677669529663687f + bias_s[(ni - mi + 7) * 15 + (nj - mj + 7)];
        if (shift > 0 && lab_s[m] != labn) acc -= 100.0f;
        float nm = fmaxf(mx, acc);
        sm = sm * __expf(mx - nm) + __expf(acc - nm);
        mx = nm;
    }

    float4 o4[8];
#pragma unroll
    for (int dq = 0; dq < 8; dq++) o4[dq] = make_float4(0.f, 0.f, 0.f, 0.f);
#pragma unroll 4
    for (int m = 0; m < 64; m++) {
        float acc = 0.0f;
#pragma unroll
        for (int dq = 0; dq < 8; dq++) {
            float4 k4 = ks4[m][dq];
            acc += q4[dq].x * k4.x + q4[dq].y * k4.y + q4[dq].z * k4.z + q4[dq].w * k4.w;
        }
        int mi = m >> 3, mj = m & 7;
        acc = acc * 0.17677669529663687f + bias_s[(ni - mi + 7) * 15 + (nj - mj + 7)];
        if (shift > 0 && lab_s[m] != labn) acc -= 100.0f;
        float p = __expf(acc - mx);
#pragma unroll
        for (int dq = 0; dq < 8; dq++) {
            float4 v4 = vs4[m][dq];
            o4[dq].x += p * v4.x; o4[dq].y += p * v4.y;
            o4[dq].z += p * v4.z; o4[dq].w += p * v4.w;
        }
    }
    float inv = 1.0f / sm;
    __nv_bfloat162* orow = (__nv_bfloat162*)(out + (size_t)(win * 64 + n) * C + head * HD);
#pragma unroll
    for (int dq = 0; dq < 8; dq++) {
        float4 o = o4[dq];
        orow[dq * 2]     = __floats2bfloat162_rn(o.x * inv, o.y * inv);
        orow[dq * 2 + 1] = __floats2bfloat162_rn(o.z * inv, o.w * inv);
    }
}

// ---------------- host ----------------
extern "C" void kernel_launch(void* const* d_in, const int* in_sizes, int n_in,
                              void* d_out, int out_size) {
    const float* x        = (const float*)d_in[0];
    const float* emb      = (const float*)d_in[3];
    const float* qkv_w    = (const float*)d_in[4];
    const float* qkv_b    = (const float*)d_in[5];
    const float* proj_w   = (const float*)d_in[6];
    const float* proj_b   = (const float*)d_in[7];
    const float* ff1_w    = (const float*)d_in[8];
    const float* ff1_b    = (const float*)d_in[9];
    const float* ff2_w    = (const float*)d_in[10];
    const float* ff2_b    = (const float*)d_in[11];
    const float* ada_w    = (const float*)d_in[12];
    const float* ada_b    = (const float*)d_in[13];
    const float* btab     = (const float*)d_in[14];
    float* xo = (float*)d_out;

    float *p_ada;
    bf16 *p_qkvb, *p_ab, *p_fb, *p_wb;
    cudaGetSymbolAddress((void**)&p_ada,  g_ada);
    cudaGetSymbolAddress((void**)&p_qkvb, g_qkvb);
    cudaGetSymbolAddress((void**)&p_ab,   g_ab);
    cudaGetSymbolAddress((void**)&p_fb,   g_fb);
    cudaGetSymbolAddress((void**)&p_wb,   g_wb);

    static int smem_set = 0;
    if (!smem_set) {
        cudaFuncSetAttribute(gemm_bf16, cudaFuncAttributeMaxDynamicSharedMemorySize, GEMM_SMEM);
        smem_set = 1;
    }

    const int NTOT = MROWS * C;
    copy_kernel<<<(NTOT + 255) / 256, 256>>>(xo, x, NTOT);

    cvt_bf16<<<(884736 + 255) / 256, 256>>>(qkv_w,  p_wb + W_QKV,  884736);
    cvt_bf16<<<(294912 + 255) / 256, 256>>>(proj_w, p_wb + W_PROJ, 294912);
    cvt_bf16<<<(1179648 + 255) / 256, 256>>>(ff1_w, p_wb + W_FF1,  1179648);
    cvt_bf16<<<(1179648 + 255) / 256, 256>>>(ff2_w, p_wb + W_FF2,  1179648);

    for (int i = 0; i < 2; i++) {
        int shift = (i == 0) ? 0 : 4;
        const bf16* qw  = p_wb + W_QKV  + (size_t)i * 1152 * C;
        const bf16* pw  = p_wb + W_PROJ + (size_t)i * C * C;
        const bf16* f1w = p_wb + W_FF1  + (size_t)i * FF * C;
        const bf16* f2w = p_wb + W_FF2  + (size_t)i * C * FF;
        const float* qb  = qkv_b  + (size_t)i * 1152;
        const float* pb  = proj_b + (size_t)i * C;
        const float* f1b = ff1_b  + (size_t)i * FF;
        const float* f2b = ff2_b  + (size_t)i * C;
        const float* aw  = ada_w  + (size_t)i * 2304 * C;
        const float* ab  = ada_b  + (size_t)i * 2304;
        const float* bt  = btab   + (size_t)i * 225 * NHEAD;

        ada_kernel<<<dim3(2304 / 256, Bsz), 256>>>(emb, aw, ab, p_ada);
        ln_mod_kernel<<<MROWS, 128>>>(xo, p_ada, p_ab, shift, 1, 384, 0);
        gemm_bf16<<<dim3(1152 / 128, MROWS / 256), 512, GEMM_SMEM>>>(
            p_ab, qw, qb, p_qkvb, nullptr, nullptr, 1152, C, OUT_BF16, 0);
        attn_kernel<<<dim3(512, NHEAD), 64>>>(p_qkvb, bt, p_ab, shift);
        gemm_bf16<<<dim3(C / 128, MROWS / 256), 512, GEMM_SMEM>>>(
            p_ab, pw, pb, nullptr, xo, p_ada, C, C, OUT_RESID_SA, shift);
        ln_mod_kernel<<<MROWS, 128>>>(xo, p_ada, p_ab, 0, 0, 1536, 1152);
        gemm_bf16<<<dim3(FF / 128, MROWS / 256), 512, GEMM_SMEM>>>(
            p_ab, f1w, f1b, p_fb, nullptr, nullptr, FF, C, OUT_GELU_BF16, 0);
        gemm_bf16<<<dim3(C / 128, MROWS / 256), 512, GEMM_SMEM>>>(
            p_fb, f2w, f2b, nullptr, xo, p_ada, C, FF, OUT_RESID_FF, 0);
    }
}

// round 16
// speedup vs baseline: 1.0482x; 1.0482x over previous
#include <cuda_runtime.h>
#include <cuda_bf16.h>
#include <cstdint>
#include <math.h>

#define Bsz   8
#define C     384
#define NHEAD 12
#define HD    32
#define FF    1536
#define MROWS 32768   // B * H * W = 8*64*64

typedef __nv_bfloat16 bf16;

// ---------------- scratch (device globals; no allocation) ----------------
__device__ float g_ada[Bsz * 2304];
__device__ float g_h[MROWS * C];                   // fp32 gemm outputs (proj/ff2)
__device__ bf16  g_qkvb[(size_t)MROWS * 1152];     // bf16 QKV
__device__ bf16  g_ab[(size_t)MROWS * C];          // bf16 activations (LN out / attn out)
__device__ bf16  g_fb[(size_t)MROWS * FF];         // bf16 FF1 output
#define WTOT 3538944
__device__ bf16  g_wb[WTOT];
#define W_QKV 0
#define W_PROJ 884736
#define W_FF1 1179648
#define W_FF2 2359296

// out kinds: 0 = fp32 store (Of), 1 = GELU -> bf16 (Ob), 2 = plain bf16 (Ob)
#define OUT_F32       0
#define OUT_GELU_BF16 1
#define OUT_BF16      2

// ---------------- copy x -> out ----------------
__global__ void copy_kernel(float* __restrict__ dst, const float* __restrict__ src, int n) {
    int i = blockIdx.x * blockDim.x + threadIdx.x;
    if (i < n) dst[i] = src[i];
}

// ---------------- fp32 -> bf16 ----------------
__global__ void cvt_bf16(const float* __restrict__ src, bf16* __restrict__ dst, int n) {
    int i = blockIdx.x * blockDim.x + threadIdx.x;
    if (i < n) dst[i] = __float2bfloat16(src[i]);
}

// ---------------- adaLN ----------------
__global__ void ada_kernel(const float* __restrict__ emb, const float* __restrict__ ada_w,
                           const float* __restrict__ ada_b, float* __restrict__ ada_out) {
    int b = blockIdx.y;
    int j = blockIdx.x * blockDim.x + threadIdx.x;
    __shared__ float se[C];
    for (int k = threadIdx.x; k < C; k += blockDim.x) {
        float e = emb[b * C + k];
        se[k] = e / (1.0f + __expf(-e));
    }
    __syncthreads();
    const float* wrow = ada_w + (size_t)j * C;
    float s = ada_b[j];
#pragma unroll 4
    for (int k = 0; k < C; k++) s += se[k] * wrow[k];
    ada_out[b * 2304 + j] = s;
}

// ---------------- LayerNorm + modulate -> bf16 (+ optional window/shift gather) ----------------
__global__ void ln_mod_kernel(const float* __restrict__ x, const float* __restrict__ ada,
                              bf16* __restrict__ out, int shift, int windowed,
                              int sc_off, int sh_off) {
    int wrow = blockIdx.x;
    int tid = threadIdx.x;
    int b, srcrow;
    if (windowed) {
        int win = wrow >> 6, n = wrow & 63;
        b = win >> 6;
        int widx = win & 63;
        int wh = widx >> 3, wwi = widx & 7, ii = n >> 3, jj = n & 7;
        int r = (wh * 8 + ii + shift) & 63;
        int cc = (wwi * 8 + jj + shift) & 63;
        srcrow = b * 4096 + r * 64 + cc;
    } else {
        b = wrow >> 12;
        srcrow = wrow;
    }
    const float* xr = x + (size_t)srcrow * C;
    float v0 = xr[tid], v1 = xr[tid + 128], v2 = xr[tid + 256];
    float s = v0 + v1 + v2;
    float q = v0 * v0 + v1 * v1 + v2 * v2;
#pragma unroll
    for (int o = 16; o > 0; o >>= 1) {
        s += __shfl_down_sync(0xffffffffu, s, o);
        q += __shfl_down_sync(0xffffffffu, q, o);
    }
    __shared__ float rs[4], rq[4], mv[2];
    int wid = tid >> 5, lane = tid & 31;
    if (lane == 0) { rs[wid] = s; rq[wid] = q; }
    __syncthreads();
    if (tid == 0) {
        float S = rs[0] + rs[1] + rs[2] + rs[3];
        float Q = rq[0] + rq[1] + rq[2] + rq[3];
        float mean = S * (1.0f / C);
        float var = Q * (1.0f / C) - mean * mean;
        mv[0] = mean;
        mv[1] = rsqrtf(var + 1e-6f);
    }
    __syncthreads();
    float mean = mv[0], rstd = mv[1];
    const float* sc = ada + b * 2304 + sc_off;
    const float* sh = ada + b * 2304 + sh_off;
    bf16* orow = out + (size_t)wrow * C;
    orow[tid]       = __float2bfloat16((v0 - mean) * rstd * (1.0f + sc[tid])       + sh[tid]);
    orow[tid + 128] = __float2bfloat16((v1 - mean) * rstd * (1.0f + sc[tid + 128]) + sh[tid + 128]);
    orow[tid + 256] = __float2bfloat16((v2 - mean) * rstd * (1.0f + sc[tid + 256]) + sh[tid + 256]);
}

// ================= bf16 tensor-core GEMM (mma.m16n8k16 + ldmatrix) =================
// BM=256, BN=128, BK=64; 512 threads / 16 warps (4x4), warp tile 64x32; 3-stage cp.async.
#define ROWB 144                       // bytes per smem row (72 bf16)
#define A_BYTES (256 * ROWB)
#define STG_BYTES (A_BYTES + 128 * ROWB)
#define GEMM_SMEM (3 * STG_BYTES)

__device__ __forceinline__ void cpasync16(uint32_t dst, const void* src) {
    asm volatile("cp.async.cg.shared.global [%0], [%1], 16;" :: "r"(dst), "l"(src));
}
__device__ __forceinline__ void cp_commit() { asm volatile("cp.async.commit_group;"); }
__device__ __forceinline__ void cp_wait0() { asm volatile("cp.async.wait_group 0;"); }
__device__ __forceinline__ void cp_wait1() { asm volatile("cp.async.wait_group 1;"); }

__device__ __forceinline__ void ldsm4(uint32_t& r0, uint32_t& r1, uint32_t& r2, uint32_t& r3,
                                      uint32_t addr) {
    asm volatile("ldmatrix.sync.aligned.m8n8.x4.shared.b16 {%0,%1,%2,%3}, [%4];"
                 : "=r"(r0), "=r"(r1), "=r"(r2), "=r"(r3) : "r"(addr));
}

__device__ __forceinline__ void mma_bf16(float* d, uint32_t a0, uint32_t a1, uint32_t a2,
                                         uint32_t a3, uint32_t b0, uint32_t b1) {
    asm volatile(
        "mma.sync.aligned.m16n8k16.row.col.f32.bf16.bf16.f32 "
        "{%0,%1,%2,%3}, {%4,%5,%6,%7}, {%8,%9}, {%0,%1,%2,%3};"
        : "+f"(d[0]), "+f"(d[1]), "+f"(d[2]), "+f"(d[3])
        : "r"(a0), "r"(a1), "r"(a2), "r"(a3), "r"(b0), "r"(b1));
}

__device__ __forceinline__ void g_load_stage(uint32_t sbase, const bf16* A, const bf16* W,
                                             int K, int kt, int bm, int bn, int tid) {
    int k0 = kt * 64;
#pragma unroll
    for (int j = 0; j < 6; j++) {
        int c = tid + j * 512;
        if (c < 2048) {
            int row = c >> 3, q = c & 7;
            cpasync16(sbase + row * ROWB + q * 16,
                      A + (size_t)(bm + row) * K + k0 + q * 8);
        } else {
            int c2 = c - 2048;
            int row = c2 >> 3, q = c2 & 7;
            cpasync16(sbase + A_BYTES + row * ROWB + q * 16,
                      W + (size_t)(bn + row) * K + k0 + q * 8);
        }
    }
}

__global__ __launch_bounds__(512, 1) void gemm_bf16(const bf16* __restrict__ A,
                                                    const bf16* __restrict__ W,
                                                    const float* __restrict__ bias,
                                                    float* __restrict__ Of,
                                                    bf16* __restrict__ Ob,
                                                    int N, int K, int outKind) {
    extern __shared__ char smem[];

    int tid = threadIdx.x;
    int warp = tid >> 5, lane = tid & 31;
    int grp = lane >> 2, qid = lane & 3;
    int wm = warp & 3, wn = warp >> 2;        // 4 x 4 warp grid
    int m_w = wm * 64, n_w = wn * 32;

    // CTA swizzle for L2 locality
    int NB = gridDim.x, MB = gridDim.y;
    int lin = blockIdx.y * NB + blockIdx.x;
    const int GM = 8;
    int gsz = GM * NB;
    int g = lin / gsz, rr = lin - g * gsz;
    int gm = min(GM, MB - g * GM);
    int mb = g * GM + rr % gm;
    int nb = rr / gm;
    int bm = mb * 256, bn = nb * 128;

    uint32_t sb0 = (uint32_t)__cvta_generic_to_shared(smem);

    int r8 = lane & 7, mat = lane >> 3;
    uint32_t aoff = (uint32_t)((m_w + r8 + (mat & 1) * 8) * ROWB + (mat >> 1) * 16);
    uint32_t boff = (uint32_t)((n_w + 8 * (mat >> 1) + r8) * ROWB + (mat & 1) * 16);

    float acc[4][4][4];
#pragma unroll
    for (int i = 0; i < 4; i++)
#pragma unroll
        for (int j = 0; j < 4; j++)
#pragma unroll
            for (int r = 0; r < 4; r++) acc[i][j][r] = 0.0f;

    int nk = K / 64;
    g_load_stage(sb0, A, W, K, 0, bm, bn, tid); cp_commit();
    if (nk > 1) { g_load_stage(sb0 + STG_BYTES, A, W, K, 1, bm, bn, tid); cp_commit(); }

    for (int kt = 0; kt < nk; kt++) {
        if (kt + 1 < nk) cp_wait1(); else cp_wait0();
        __syncthreads();
        if (kt + 2 < nk) {
            g_load_stage(sb0 + ((kt + 2) % 3) * STG_BYTES, A, W, K, kt + 2, bm, bn, tid);
            cp_commit();
        }
        uint32_t sA = sb0 + (kt % 3) * STG_BYTES;
        uint32_t sB = sA + A_BYTES;
#pragma unroll
        for (int ks = 0; ks < 4; ks++) {
            uint32_t ka = ks * 32;
            uint32_t af[4][4], bfr[2][4];
#pragma unroll
            for (int i = 0; i < 4; i++)
                ldsm4(af[i][0], af[i][1], af[i][2], af[i][3], sA + aoff + i * (16 * ROWB) + ka);
#pragma unroll
            for (int jp = 0; jp < 2; jp++)
                ldsm4(bfr[jp][0], bfr[jp][1], bfr[jp][2], bfr[jp][3],
                      sB + boff + jp * (16 * ROWB) + ka);
#pragma unroll
            for (int i = 0; i < 4; i++)
#pragma unroll
                for (int j = 0; j < 4; j++) {
                    int jp = j >> 1, jl = j & 1;
                    mma_bf16(acc[i][j], af[i][0], af[i][1], af[i][2], af[i][3],
                             bfr[jp][2 * jl], bfr[jp][2 * jl + 1]);
                }
        }
    }

    // epilogue
#pragma unroll
    for (int i = 0; i < 4; i++) {
#pragma unroll
        for (int j = 0; j < 4; j++) {
            int row = bm + m_w + 16 * i + grp;
            int col = bn + n_w + 8 * j + 2 * qid;
            float b0 = __ldg(&bias[col]), b1 = __ldg(&bias[col + 1]);
            float v0 = acc[i][j][0] + b0, v1 = acc[i][j][1] + b1;
            float v2 = acc[i][j][2] + b0, v3 = acc[i][j][3] + b1;
            if (outKind == OUT_F32) {
                *(float2*)&Of[(size_t)row * N + col] = make_float2(v0, v1);
                *(float2*)&Of[(size_t)(row + 8) * N + col] = make_float2(v2, v3);
            } else {
                if (outKind == OUT_GELU_BF16) {
                    v0 = 0.5f * v0 * (1.0f + erff(v0 * 0.70710678118654752f));
                    v1 = 0.5f * v1 * (1.0f + erff(v1 * 0.70710678118654752f));
                    v2 = 0.5f * v2 * (1.0f + erff(v2 * 0.70710678118654752f));
                    v3 = 0.5f * v3 * (1.0f + erff(v3 * 0.70710678118654752f));
                }
                *(__nv_bfloat162*)&Ob[(size_t)row * N + col] = __floats2bfloat162_rn(v0, v1);
                *(__nv_bfloat162*)&Ob[(size_t)(row + 8) * N + col] = __floats2bfloat162_rn(v2, v3);
            }
        }
    }
}

// ---------------- window attention: bf16 in, two-pass online softmax, bf16 out ----------------
__device__ __forceinline__ int regid(int r) { return r < 56 ? 0 : (r < 60 ? 1 : 2); }

__global__ __launch_bounds__(64, 8) void attn_kernel(const bf16* __restrict__ qkv,
                                                     const float* __restrict__ bias_table,
                                                     bf16* __restrict__ out, int shift) {
    int win = blockIdx.x;
    int head = blockIdx.y;
    int n = threadIdx.x;
    __shared__ float4 ks4[64][8];
    __shared__ float4 vs4[64][8];
    __shared__ float bias_s[225];
    __shared__ int lab_s[64];

    size_t base = (size_t)win * 64 * 1152 + head * HD;
#pragma unroll
    for (int i = 0; i < 8; i++) {
        int idx = n + i * 64;          // 0..511
        int m = (idx >> 2) & 63, q = idx & 3;
        const __nv_bfloat162* src = (idx < 256)
            ? (const __nv_bfloat162*)&qkv[base + (size_t)m * 1152 + 384 + q * 8]
            : (const __nv_bfloat162*)&qkv[base + (size_t)m * 1152 + 768 + q * 8];
        float2 f0 = __bfloat1622float2(src[0]);
        float2 f1 = __bfloat1622float2(src[1]);
        float2 f2 = __bfloat1622float2(src[2]);
        float2 f3 = __bfloat1622float2(src[3]);
        float4* dst = (idx < 256) ? &ks4[m][q * 2] : &vs4[m][q * 2];
        dst[0] = make_float4(f0.x, f0.y, f1.x, f1.y);
        dst[1] = make_float4(f2.x, f2.y, f3.x, f3.y);
    }
    float4 q4[8];
#pragma unroll
    for (int q = 0; q < 4; q++) {
        const __nv_bfloat162* src = (const __nv_bfloat162*)&qkv[base + (size_t)n * 1152 + q * 8];
        float2 f0 = __bfloat1622float2(src[0]);
        float2 f1 = __bfloat1622float2(src[1]);
        float2 f2 = __bfloat1622float2(src[2]);
        float2 f3 = __bfloat1622float2(src[3]);
        q4[q * 2]     = make_float4(f0.x, f0.y, f1.x, f1.y);
        q4[q * 2 + 1] = make_float4(f2.x, f2.y, f3.x, f3.y);
    }
    for (int i = n; i < 225; i += 64) bias_s[i] = bias_table[i * NHEAD + head];

    int widx = win & 63;
    int wh = widx >> 3, wwi = widx & 7;
    {
        int ii = n >> 3, jj = n & 7;
        lab_s[n] = regid(wh * 8 + ii) * 3 + regid(wwi * 8 + jj);
    }
    __syncthreads();

    int ni = n >> 3, nj = n & 7;
    int labn = lab_s[n];

    float mx = -1e30f, sm = 0.0f;
#pragma unroll 4
    for (int m = 0; m < 64; m++) {
        float acc = 0.0f;
#pragma unroll
        for (int dq = 0; dq < 8; dq++) {
            float4 k4 = ks4[m][dq];
            acc += q4[dq].x * k4.x + q4[dq].y * k4.y + q4[dq].z * k4.z + q4[dq].w * k4.w;
        }
        int mi = m >> 3, mj = m & 7;
        acc = acc * 0.17677669529663687f + bias_s[(ni - mi + 7) * 15 + (nj - mj + 7)];
        if (shift > 0 && lab_s[m] != labn) acc -= 100.0f;
        float nm = fmaxf(mx, acc);
        sm = sm * __expf(mx - nm) + __expf(acc - nm);
        mx = nm;
    }

    float4 o4[8];
#pragma unroll
    for (int dq = 0; dq < 8; dq++) o4[dq] = make_float4(0.f, 0.f, 0.f, 0.f);
#pragma unroll 4
    for (int m = 0; m < 64; m++) {
        float acc = 0.0f;
#pragma unroll
        for (int dq = 0; dq < 8; dq++) {
            float4 k4 = ks4[m][dq];
            acc += q4[dq].x * k4.x + q4[dq].y * k4.y + q4[dq].z * k4.z + q4[dq].w * k4.w;
        }
        int mi = m >> 3, mj = m & 7;
        acc = acc * 0.17677669529663687f + bias_s[(ni - mi + 7) * 15 + (nj - mj + 7)];
        if (shift > 0 && lab_s[m] != labn) acc -= 100.0f;
        float p = __expf(acc - mx);
#pragma unroll
        for (int dq = 0; dq < 8; dq++) {
            float4 v4 = vs4[m][dq];
            o4[dq].x += p * v4.x; o4[dq].y += p * v4.y;
            o4[dq].z += p * v4.z; o4[dq].w += p * v4.w;
        }
    }
    float inv = 1.0f / sm;
    __nv_bfloat162* orow = (__nv_bfloat162*)(out + (size_t)(win * 64 + n) * C + head * HD);
#pragma unroll
    for (int dq = 0; dq < 8; dq++) {
        float4 o = o4[dq];
        orow[dq * 2]     = __floats2bfloat162_rn(o.x * inv, o.y * inv);
        orow[dq * 2 + 1] = __floats2bfloat162_rn(o.z * inv, o.w * inv);
    }
}

// ---------------- residual scatter (SA path), float4 ----------------
__global__ void resid_sa_kernel(float* __restrict__ x, const float* __restrict__ pout,
                                const float* __restrict__ ada, int shift) {
    int idx = blockIdx.x * blockDim.x + threadIdx.x;   // over NTOT/4
    if (idx >= MROWS * C / 4) return;
    int wrow = idx / (C / 4), cq = idx - wrow * (C / 4);
    int c = cq * 4;
    int win = wrow >> 6, n = wrow & 63;
    int b = win >> 6, widx = win & 63;
    int wh = widx >> 3, wwi = widx & 7, ii = n >> 3, jj = n & 7;
    int r = (wh * 8 + ii + shift) & 63;
    int cc = (wwi * 8 + jj + shift) & 63;
    size_t drow = (size_t)b * 4096 + r * 64 + cc;
    float4 g = *(const float4*)&ada[b * 2304 + 768 + c];
    float4 p = *(const float4*)&pout[(size_t)wrow * C + c];
    float4* xp = (float4*)&x[drow * C + c];
    float4 xv = *xp;
    xv.x += g.x * p.x; xv.y += g.y * p.y; xv.z += g.z * p.z; xv.w += g.w * p.w;
    *xp = xv;
}

// ---------------- residual (FF path), float4 ----------------
__global__ void resid_ff_kernel(float* __restrict__ x, const float* __restrict__ fout,
                                const float* __restrict__ ada) {
    int idx = blockIdx.x * blockDim.x + threadIdx.x;   // over NTOT/4
    if (idx >= MROWS * C / 4) return;
    int row = idx / (C / 4), cq = idx - row * (C / 4);
    int c = cq * 4;
    int b = row >> 12;
    float4 g = *(const float4*)&ada[b * 2304 + 1920 + c];
    float4 f = *(const float4*)&fout[(size_t)row * C + c];
    float4* xp = (float4*)&x[(size_t)row * C + c];
    float4 xv = *xp;
    xv.x += g.x * f.x; xv.y += g.y * f.y; xv.z += g.z * f.z; xv.w += g.w * f.w;
    *xp = xv;
}

// ---------------- host ----------------
extern "C" void kernel_launch(void* const* d_in, const int* in_sizes, int n_in,
                              void* d_out, int out_size) {
    const float* x        = (const float*)d_in[0];
    const float* emb      = (const float*)d_in[3];
    const float* qkv_w    = (const float*)d_in[4];
    const float* qkv_b    = (const float*)d_in[5];
    const float* proj_w   = (const float*)d_in[6];
    const float* proj_b   = (const float*)d_in[7];
    const float* ff1_w    = (const float*)d_in[8];
    const float* ff1_b    = (const float*)d_in[9];
    const float* ff2_w    = (const float*)d_in[10];
    const float* ff2_b    = (const float*)d_in[11];
    const float* ada_w    = (const float*)d_in[12];
    const float* ada_b    = (const float*)d_in[13];
    const float* btab     = (const float*)d_in[14];
    float* xo = (float*)d_out;

    float *p_ada, *p_h;
    bf16 *p_qkvb, *p_ab, *p_fb, *p_wb;
    cudaGetSymbolAddress((void**)&p_ada,  g_ada);
    cudaGetSymbolAddress((void**)&p_h,    g_h);
    cudaGetSymbolAddress((void**)&p_qkvb, g_qkvb);
    cudaGetSymbolAddress((void**)&p_ab,   g_ab);
    cudaGetSymbolAddress((void**)&p_fb,   g_fb);
    cudaGetSymbolAddress((void**)&p_wb,   g_wb);

    static int smem_set = 0;
    if (!smem_set) {
        cudaFuncSetAttribute(gemm_bf16, cudaFuncAttributeMaxDynamicSharedMemorySize, GEMM_SMEM);
        smem_set = 1;
    }

    const int NTOT = MROWS * C;
    const int NQ = NTOT / 4;
    copy_kernel<<<(NTOT + 255) / 256, 256>>>(xo, x, NTOT);

    cvt_bf16<<<(884736 + 255) / 256, 256>>>(qkv_w,  p_wb + W_QKV,  884736);
    cvt_bf16<<<(294912 + 255) / 256, 256>>>(proj_w, p_wb + W_PROJ, 294912);
    cvt_bf16<<<(1179648 + 255) / 256, 256>>>(ff1_w, p_wb + W_FF1,  1179648);
    cvt_bf16<<<(1179648 + 255) / 256, 256>>>(ff2_w, p_wb + W_FF2,  1179648);

    for (int i = 0; i < 2; i++) {
        int shift = (i == 0) ? 0 : 4;
        const bf16* qw  = p_wb + W_QKV  + (size_t)i * 1152 * C;
        const bf16* pw  = p_wb + W_PROJ + (size_t)i * C * C;
        const bf16* f1w = p_wb + W_FF1  + (size_t)i * FF * C;
        const bf16* f2w = p_wb + W_FF2  + (size_t)i * C * FF;
        const float* qb  = qkv_b  + (size_t)i * 1152;
        const float* pb  = proj_b + (size_t)i * C;
        const float* f1b = ff1_b  + (size_t)i * FF;
        const float* f2b = ff2_b  + (size_t)i * C;
        const float* aw  = ada_w  + (size_t)i * 2304 * C;
        const float* ab  = ada_b  + (size_t)i * 2304;
        const float* bt  = btab   + (size_t)i * 225 * NHEAD;

        ada_kernel<<<dim3(2304 / 256, Bsz), 256>>>(emb, aw, ab, p_ada);
        ln_mod_kernel<<<MROWS, 128>>>(xo, p_ada, p_ab, shift, 1, 384, 0);
        gemm_bf16<<<dim3(1152 / 128, MROWS / 256), 512, GEMM_SMEM>>>(
            p_ab, qw, qb, nullptr, p_qkvb, 1152, C, OUT_BF16);
        attn_kernel<<<dim3(512, NHEAD), 64>>>(p_qkvb, bt, p_ab, shift);
        gemm_bf16<<<dim3(C / 128, MROWS / 256), 512, GEMM_SMEM>>>(
            p_ab, pw, pb, p_h, nullptr, C, C, OUT_F32);
        resid_sa_kernel<<<(NQ + 255) / 256, 256>>>(xo, p_h, p_ada, shift);
        ln_mod_kernel<<<MROWS, 128>>>(xo, p_ada, p_ab, 0, 0, 1536, 1152);
        gemm_bf16<<<dim3(FF / 128, MROWS / 256), 512, GEMM_SMEM>>>(
            p_ab, f1w, f1b, nullptr, p_fb, FF, C, OUT_GELU_BF16);
        gemm_bf16<<<dim3(C / 128, MROWS / 256), 512, GEMM_SMEM>>>(
            p_fb, f2w, f2b, p_h, nullptr, C, FF, OUT_F32);
        resid_ff_kernel<<<(NQ + 255) / 256, 256>>>(xo, p_h, p_ada);
    }
}

// round 17
// speedup vs baseline: 1.0908x; 1.0406x over previous
#include <cuda_runtime.h>
#include <cuda_bf16.h>
#include <cstdint>
#include <math.h>

#define Bsz   8
#define C     384
#define NHEAD 12
#define HD    32
#define FF    1536
#define MROWS 32768   // B * H * W = 8*64*64

typedef __nv_bfloat16 bf16;

// ---------------- scratch (device globals; no allocation) ----------------
__device__ float g_ada[Bsz * 2304];
__device__ float g_h[MROWS * C];                   // fp32 gemm outputs (proj/ff2)
__device__ float g_qkv[(size_t)MROWS * 1152];      // fp32 QKV
__device__ bf16  g_ab[(size_t)MROWS * C];          // bf16 activations (LN out / attn out)
__device__ bf16  g_fb[(size_t)MROWS * FF];         // bf16 FF1 output
#define WTOT 3538944
__device__ bf16  g_wb[WTOT];
#define W_QKV 0
#define W_PROJ 884736
#define W_FF1 1179648
#define W_FF2 2359296

// out kinds: 0 = fp32 store (Of), 1 = GELU -> bf16 (Ob), 2 = plain bf16 (Ob)
#define OUT_F32       0
#define OUT_GELU_BF16 1
#define OUT_BF16      2

// ---------------- copy x -> out ----------------
__global__ void copy_kernel(float* __restrict__ dst, const float* __restrict__ src, int n) {
    int i = blockIdx.x * blockDim.x + threadIdx.x;
    if (i < n) dst[i] = src[i];
}

// ---------------- fp32 -> bf16 ----------------
__global__ void cvt_bf16(const float* __restrict__ src, bf16* __restrict__ dst, int n) {
    int i = blockIdx.x * blockDim.x + threadIdx.x;
    if (i < n) dst[i] = __float2bfloat16(src[i]);
}

// ---------------- adaLN ----------------
__global__ void ada_kernel(const float* __restrict__ emb, const float* __restrict__ ada_w,
                           const float* __restrict__ ada_b, float* __restrict__ ada_out) {
    int b = blockIdx.y;
    int j = blockIdx.x * blockDim.x + threadIdx.x;
    __shared__ float se[C];
    for (int k = threadIdx.x; k < C; k += blockDim.x) {
        float e = emb[b * C + k];
        se[k] = e / (1.0f + __expf(-e));
    }
    __syncthreads();
    const float* wrow = ada_w + (size_t)j * C;
    float s = ada_b[j];
#pragma unroll 4
    for (int k = 0; k < C; k++) s += se[k] * wrow[k];
    ada_out[b * 2304 + j] = s;
}

// ---------------- LayerNorm + modulate -> bf16 (+ optional window/shift gather) ----------------
__global__ void ln_mod_kernel(const float* __restrict__ x, const float* __restrict__ ada,
                              bf16* __restrict__ out, int shift, int windowed,
                              int sc_off, int sh_off) {
    int wrow = blockIdx.x;
    int tid = threadIdx.x;
    int b, srcrow;
    if (windowed) {
        int win = wrow >> 6, n = wrow & 63;
        b = win >> 6;
        int widx = win & 63;
        int wh = widx >> 3, wwi = widx & 7, ii = n >> 3, jj = n & 7;
        int r = (wh * 8 + ii + shift) & 63;
        int cc = (wwi * 8 + jj + shift) & 63;
        srcrow = b * 4096 + r * 64 + cc;
    } else {
        b = wrow >> 12;
        srcrow = wrow;
    }
    const float* xr = x + (size_t)srcrow * C;
    float v0 = xr[tid], v1 = xr[tid + 128], v2 = xr[tid + 256];
    float s = v0 + v1 + v2;
    float q = v0 * v0 + v1 * v1 + v2 * v2;
#pragma unroll
    for (int o = 16; o > 0; o >>= 1) {
        s += __shfl_down_sync(0xffffffffu, s, o);
        q += __shfl_down_sync(0xffffffffu, q, o);
    }
    __shared__ float rs[4], rq[4], mv[2];
    int wid = tid >> 5, lane = tid & 31;
    if (lane == 0) { rs[wid] = s; rq[wid] = q; }
    __syncthreads();
    if (tid == 0) {
        float S = rs[0] + rs[1] + rs[2] + rs[3];
        float Q = rq[0] + rq[1] + rq[2] + rq[3];
        float mean = S * (1.0f / C);
        float var = Q * (1.0f / C) - mean * mean;
        mv[0] = mean;
        mv[1] = rsqrtf(var + 1e-6f);
    }
    __syncthreads();
    float mean = mv[0], rstd = mv[1];
    const float* sc = ada + b * 2304 + sc_off;
    const float* sh = ada + b * 2304 + sh_off;
    bf16* orow = out + (size_t)wrow * C;
    orow[tid]       = __float2bfloat16((v0 - mean) * rstd * (1.0f + sc[tid])       + sh[tid]);
    orow[tid + 128] = __float2bfloat16((v1 - mean) * rstd * (1.0f + sc[tid + 128]) + sh[tid + 128]);
    orow[tid + 256] = __float2bfloat16((v2 - mean) * rstd * (1.0f + sc[tid + 256]) + sh[tid + 256]);
}

// ================= bf16 tensor-core GEMM (mma.m16n8k16 + ldmatrix) =================
// BM=128, BN=128, BK=64; 256 threads / 8 warps (4x2), warp tile 32x64;
// 3-stage cp.async; 2 CTAs per SM to overlap barrier bubbles.
#define ROWB 144                       // bytes per smem row (72 bf16)
#define A_BYTES (128 * ROWB)
#define STG_BYTES (A_BYTES + 128 * ROWB)
#define GEMM_SMEM (3 * STG_BYTES)      // 110592 B per CTA

__device__ __forceinline__ void cpasync16(uint32_t dst, const void* src) {
    asm volatile("cp.async.cg.shared.global [%0], [%1], 16;" :: "r"(dst), "l"(src));
}
__device__ __forceinline__ void cp_commit() { asm volatile("cp.async.commit_group;"); }
__device__ __forceinline__ void cp_wait0() { asm volatile("cp.async.wait_group 0;"); }
__device__ __forceinline__ void cp_wait1() { asm volatile("cp.async.wait_group 1;"); }

__device__ __forceinline__ void ldsm4(uint32_t& r0, uint32_t& r1, uint32_t& r2, uint32_t& r3,
                                      uint32_t addr) {
    asm volatile("ldmatrix.sync.aligned.m8n8.x4.shared.b16 {%0,%1,%2,%3}, [%4];"
                 : "=r"(r0), "=r"(r1), "=r"(r2), "=r"(r3) : "r"(addr));
}

__device__ __forceinline__ void mma_bf16(float* d, uint32_t a0, uint32_t a1, uint32_t a2,
                                         uint32_t a3, uint32_t b0, uint32_t b1) {
    asm volatile(
        "mma.sync.aligned.m16n8k16.row.col.f32.bf16.bf16.f32 "
        "{%0,%1,%2,%3}, {%4,%5,%6,%7}, {%8,%9}, {%0,%1,%2,%3};"
        : "+f"(d[0]), "+f"(d[1]), "+f"(d[2]), "+f"(d[3])
        : "r"(a0), "r"(a1), "r"(a2), "r"(a3), "r"(b0), "r"(b1));
}

__device__ __forceinline__ void g_load_stage(uint32_t sbase, const bf16* A, const bf16* W,
                                             int K, int kt, int bm, int bn, int tid) {
    int k0 = kt * 64;
#pragma unroll
    for (int j = 0; j < 8; j++) {
        int c = tid + j * 256;                // 0..2047
        int row = (c >> 3) & 127, q = c & 7;
        if (c < 1024)
            cpasync16(sbase + row * ROWB + q * 16,
                      A + (size_t)(bm + row) * K + k0 + q * 8);
        else
            cpasync16(sbase + A_BYTES + row * ROWB + q * 16,
                      W + (size_t)(bn + row) * K + k0 + q * 8);
    }
}

__global__ __launch_bounds__(256, 2) void gemm_bf16(const bf16* __restrict__ A,
                                                    const bf16* __restrict__ W,
                                                    const float* __restrict__ bias,
                                                    float* __restrict__ Of,
                                                    bf16* __restrict__ Ob,
                                                    int N, int K, int outKind) {
    extern __shared__ char smem[];

    int tid = threadIdx.x;
    int warp = tid >> 5, lane = tid & 31;
    int grp = lane >> 2, qid = lane & 3;
    int wm = warp & 3, wn = warp >> 2;        // 4 x 2 warp grid
    int m_w = wm * 32, n_w = wn * 64;

    // CTA swizzle for L2 locality
    int NB = gridDim.x, MB = gridDim.y;
    int lin = blockIdx.y * NB + blockIdx.x;
    const int GM = 8;
    int gsz = GM * NB;
    int g = lin / gsz, rr = lin - g * gsz;
    int gm = min(GM, MB - g * GM);
    int mb = g * GM + rr % gm;
    int nb = rr / gm;
    int bm = mb * 128, bn = nb * 128;

    uint32_t sb0 = (uint32_t)__cvta_generic_to_shared(smem);

    int r8 = lane & 7, mat = lane >> 3;
    uint32_t aoff = (uint32_t)((m_w + r8 + (mat & 1) * 8) * ROWB + (mat >> 1) * 16);
    uint32_t boff = (uint32_t)((n_w + 8 * (mat >> 1) + r8) * ROWB + (mat & 1) * 16);

    float acc[2][8][4];
#pragma unroll
    for (int i = 0; i < 2; i++)
#pragma unroll
        for (int j = 0; j < 8; j++)
#pragma unroll
            for (int r = 0; r < 4; r++) acc[i][j][r] = 0.0f;

    int nk = K / 64;
    g_load_stage(sb0, A, W, K, 0, bm, bn, tid); cp_commit();
    if (nk > 1) { g_load_stage(sb0 + STG_BYTES, A, W, K, 1, bm, bn, tid); cp_commit(); }

    for (int kt = 0; kt < nk; kt++) {
        if (kt + 1 < nk) cp_wait1(); else cp_wait0();
        __syncthreads();
        if (kt + 2 < nk) {
            g_load_stage(sb0 + ((kt + 2) % 3) * STG_BYTES, A, W, K, kt + 2, bm, bn, tid);
            cp_commit();
        }
        uint32_t sA = sb0 + (kt % 3) * STG_BYTES;
        uint32_t sB = sA + A_BYTES;
#pragma unroll
        for (int ks = 0; ks < 4; ks++) {
            uint32_t ka = ks * 32;            // 16 bf16 = 32 bytes per k-step
            uint32_t af[2][4], bfr[4][4];
#pragma unroll
            for (int i = 0; i < 2; i++)
                ldsm4(af[i][0], af[i][1], af[i][2], af[i][3], sA + aoff + i * (16 * ROWB) + ka);
#pragma unroll
            for (int jp = 0; jp < 4; jp++)
                ldsm4(bfr[jp][0], bfr[jp][1], bfr[jp][2], bfr[jp][3],
                      sB + boff + jp * (16 * ROWB) + ka);
#pragma unroll
            for (int i = 0; i < 2; i++)
#pragma unroll
                for (int j = 0; j < 8; j++) {
                    int jp = j >> 1, jl = j & 1;
                    mma_bf16(acc[i][j], af[i][0], af[i][1], af[i][2], af[i][3],
                             bfr[jp][2 * jl], bfr[jp][2 * jl + 1]);
                }
        }
        __syncthreads();
    }

    // epilogue
#pragma unroll
    for (int i = 0; i < 2; i++) {
#pragma unroll
        for (int j = 0; j < 8; j++) {
            int row = bm + m_w + 16 * i + grp;
            int col = bn + n_w + 8 * j + 2 * qid;
            float b0 = __ldg(&bias[col]), b1 = __ldg(&bias[col + 1]);
            float v0 = acc[i][j][0] + b0, v1 = acc[i][j][1] + b1;
            float v2 = acc[i][j][2] + b0, v3 = acc[i][j][3] + b1;
            if (outKind == OUT_F32) {
                *(float2*)&Of[(size_t)row * N + col] = make_float2(v0, v1);
                *(float2*)&Of[(size_t)(row + 8) * N + col] = make_float2(v2, v3);
            } else {
                if (outKind == OUT_GELU_BF16) {
                    v0 = 0.5f * v0 * (1.0f + erff(v0 * 0.70710678118654752f));
                    v1 = 0.5f * v1 * (1.0f + erff(v1 * 0.70710678118654752f));
                    v2 = 0.5f * v2 * (1.0f + erff(v2 * 0.70710678118654752f));
                    v3 = 0.5f * v3 * (1.0f + erff(v3 * 0.70710678118654752f));
                }
                *(__nv_bfloat162*)&Ob[(size_t)row * N + col] = __floats2bfloat162_rn(v0, v1);
                *(__nv_bfloat162*)&Ob[(size_t)(row + 8) * N + col] = __floats2bfloat162_rn(v2, v3);
            }
        }
    }
}

// ---------------- window attention: fp32 in, two-pass online softmax, bf16 out ----------------
__device__ __forceinline__ int regid(int r) { return r < 56 ? 0 : (r < 60 ? 1 : 2); }

__global__ __launch_bounds__(64, 8) void attn_kernel(const float* __restrict__ qkv,
                                                     const float* __restrict__ bias_table,
                                                     bf16* __restrict__ out, int shift) {
    int win = blockIdx.x;
    int head = blockIdx.y;
    int n = threadIdx.x;
    __shared__ float4 ks4[64][8];
    __shared__ float4 vs4[64][8];
    __shared__ float bias_s[225];
    __shared__ int lab_s[64];

    size_t base = (size_t)win * 64 * 1152 + head * HD;
#pragma unroll
    for (int i = 0; i < 8; i++) {
        int idx = n + i * 64;
        int m = idx >> 3, dq = idx & 7;
        ks4[m][dq] = *(const float4*)&qkv[base + (size_t)m * 1152 + 384 + dq * 4];
        vs4[m][dq] = *(const float4*)&qkv[base + (size_t)m * 1152 + 768 + dq * 4];
    }
    float4 q4[8];
#pragma unroll
    for (int dq = 0; dq < 8; dq++) q4[dq] = *(const float4*)&qkv[base + (size_t)n * 1152 + dq * 4];
    for (int i = n; i < 225; i += 64) bias_s[i] = bias_table[i * NHEAD + head];

    int widx = win & 63;
    int wh = widx >> 3, wwi = widx & 7;
    {
        int ii = n >> 3, jj = n & 7;
        lab_s[n] = regid(wh * 8 + ii) * 3 + regid(wwi * 8 + jj);
    }
    __syncthreads();

    int ni = n >> 3, nj = n & 7;
    int labn = lab_s[n];

    float mx = -1e30f, sm = 0.0f;
#pragma unroll 4
    for (int m = 0; m < 64; m++) {
        float acc = 0.0f;
#pragma unroll
        for (int dq = 0; dq < 8; dq++) {
            float4 k4 = ks4[m][dq];
            acc += q4[dq].x * k4.x + q4[dq].y * k4.y + q4[dq].z * k4.z + q4[dq].w * k4.w;
        }
        int mi = m >> 3, mj = m & 7;
        acc = acc * 0.17677669529663687f + bias_s[(ni - mi + 7) * 15 + (nj - mj + 7)];
        if (shift > 0 && lab_s[m] != labn) acc -= 100.0f;
        float nm = fmaxf(mx, acc);
        sm = sm * __expf(mx - nm) + __expf(acc - nm);
        mx = nm;
    }

    float4 o4[8];
#pragma unroll
    for (int dq = 0; dq < 8; dq++) o4[dq] = make_float4(0.f, 0.f, 0.f, 0.f);
#pragma unroll 4
    for (int m = 0; m < 64; m++) {
        float acc = 0.0f;
#pragma unroll
        for (int dq = 0; dq < 8; dq++) {
            float4 k4 = ks4[m][dq];
            acc += q4[dq].x * k4.x + q4[dq].y * k4.y + q4[dq].z * k4.z + q4[dq].w * k4.w;
        }
        int mi = m >> 3, mj = m & 7;
        acc = acc * 0.17677669529663687f + bias_s[(ni - mi + 7) * 15 + (nj - mj + 7)];
        if (shift > 0 && lab_s[m] != labn) acc -= 100.0f;
        float p = __expf(acc - mx);
#pragma unroll
        for (int dq = 0; dq < 8; dq++) {
            float4 v4 = vs4[m][dq];
            o4[dq].x += p * v4.x; o4[dq].y += p * v4.y;
            o4[dq].z += p * v4.z; o4[dq].w += p * v4.w;
        }
    }
    float inv = 1.0f / sm;
    __nv_bfloat162* orow = (__nv_bfloat162*)(out + (size_t)(win * 64 + n) * C + head * HD);
#pragma unroll
    for (int dq = 0; dq < 8; dq++) {
        float4 o = o4[dq];
        orow[dq * 2]     = __floats2bfloat162_rn(o.x * inv, o.y * inv);
        orow[dq * 2 + 1] = __floats2bfloat162_rn(o.z * inv, o.w * inv);
    }
}

// ---------------- residual scatter (SA path), float4 ----------------
__global__ void resid_sa_kernel(float* __restrict__ x, const float* __restrict__ pout,
                                const float* __restrict__ ada, int shift) {
    int idx = blockIdx.x * blockDim.x + threadIdx.x;   // over NTOT/4
    if (idx >= MROWS * C / 4) return;
    int wrow = idx / (C / 4), cq = idx - wrow * (C / 4);
    int c = cq * 4;
    int win = wrow >> 6, n = wrow & 63;
    int b = win >> 6, widx = win & 63;
    int wh = widx >> 3, wwi = widx & 7, ii = n >> 3, jj = n & 7;
    int r = (wh * 8 + ii + shift) & 63;
    int cc = (wwi * 8 + jj + shift) & 63;
    size_t drow = (size_t)b * 4096 + r * 64 + cc;
    float4 g = *(const float4*)&ada[b * 2304 + 768 + c];
    float4 p = *(const float4*)&pout[(size_t)wrow * C + c];
    float4* xp = (float4*)&x[drow * C + c];
    float4 xv = *xp;
    xv.x += g.x * p.x; xv.y += g.y * p.y; xv.z += g.z * p.z; xv.w += g.w * p.w;
    *xp = xv;
}

// ---------------- residual (FF path), float4 ----------------
__global__ void resid_ff_kernel(float* __restrict__ x, const float* __restrict__ fout,
                                const float* __restrict__ ada) {
    int idx = blockIdx.x * blockDim.x + threadIdx.x;   // over NTOT/4
    if (idx >= MROWS * C / 4) return;
    int row = idx / (C / 4), cq = idx - row * (C / 4);
    int c = cq * 4;
    int b = row >> 12;
    float4 g = *(const float4*)&ada[b * 2304 + 1920 + c];
    float4 f = *(const float4*)&fout[(size_t)row * C + c];
    float4* xp = (float4*)&x[(size_t)row * C + c];
    float4 xv = *xp;
    xv.x += g.x * f.x; xv.y += g.y * f.y; xv.z += g.z * f.z; xv.w += g.w * f.w;
    *xp = xv;
}

// ---------------- host ----------------
extern "C" void kernel_launch(void* const* d_in, const int* in_sizes, int n_in,
                              void* d_out, int out_size) {
    const float* x        = (const float*)d_in[0];
    const float* emb      = (const float*)d_in[3];
    const float* qkv_w    = (const float*)d_in[4];
    const float* qkv_b    = (const float*)d_in[5];
    const float* proj_w   = (const float*)d_in[6];
    const float* proj_b   = (const float*)d_in[7];
    const float* ff1_w    = (const float*)d_in[8];
    const float* ff1_b    = (const float*)d_in[9];
    const float* ff2_w    = (const float*)d_in[10];
    const float* ff2_b    = (const float*)d_in[11];
    const float* ada_w    = (const float*)d_in[12];
    const float* ada_b    = (const float*)d_in[13];
    const float* btab     = (const float*)d_in[14];
    float* xo = (float*)d_out;

    float *p_ada, *p_h, *p_qkv;
    bf16 *p_ab, *p_fb, *p_wb;
    cudaGetSymbolAddress((void**)&p_ada, g_ada);
    cudaGetSymbolAddress((void**)&p_h,   g_h);
    cudaGetSymbolAddress((void**)&p_qkv, g_qkv);
    cudaGetSymbolAddress((void**)&p_ab,  g_ab);
    cudaGetSymbolAddress((void**)&p_fb,  g_fb);
    cudaGetSymbolAddress((void**)&p_wb,  g_wb);

    static int smem_set = 0;
    if (!smem_set) {
        cudaFuncSetAttribute(gemm_bf16, cudaFuncAttributeMaxDynamicSharedMemorySize, GEMM_SMEM);
        smem_set = 1;
    }

    const int NTOT = MROWS * C;
    const int NQ = NTOT / 4;
    copy_kernel<<<(NTOT + 255) / 256, 256>>>(xo, x, NTOT);

    cvt_bf16<<<(884736 + 255) / 256, 256>>>(qkv_w,  p_wb + W_QKV,  884736);
    cvt_bf16<<<(294912 + 255) / 256, 256>>>(proj_w, p_wb + W_PROJ, 294912);
    cvt_bf16<<<(1179648 + 255) / 256, 256>>>(ff1_w, p_wb + W_FF1,  1179648);
    cvt_bf16<<<(1179648 + 255) / 256, 256>>>(ff2_w, p_wb + W_FF2,  1179648);

    for (int i = 0; i < 2; i++) {
        int shift = (i == 0) ? 0 : 4;
        const bf16* qw  = p_wb + W_QKV  + (size_t)i * 1152 * C;
        const bf16* pw  = p_wb + W_PROJ + (size_t)i * C * C;
        const bf16* f1w = p_wb + W_FF1  + (size_t)i * FF * C;
        const bf16* f2w = p_wb + W_FF2  + (size_t)i * C * FF;
        const float* qb  = qkv_b  + (size_t)i * 1152;
        const float* pb  = proj_b + (size_t)i * C;
        const float* f1b = ff1_b  + (size_t)i * FF;
        const float* f2b = ff2_b  + (size_t)i * C;
        const float* aw  = ada_w  + (size_t)i * 2304 * C;
        const float* ab  = ada_b  + (size_t)i * 2304;
        const float* bt  = btab   + (size_t)i * 225 * NHEAD;

        ada_kernel<<<dim3(2304 / 256, Bsz), 256>>>(emb, aw, ab, p_ada);
        ln_mod_kernel<<<MROWS, 128>>>(xo, p_ada, p_ab, shift, 1, 384, 0);
        gemm_bf16<<<dim3(1152 / 128, MROWS / 128), 256, GEMM_SMEM>>>(
            p_ab, qw, qb, p_qkv, nullptr, 1152, C, OUT_F32);
        attn_kernel<<<dim3(512, NHEAD), 64>>>(p_qkv, bt, p_ab, shift);
        gemm_bf16<<<dim3(C / 128, MROWS / 128), 256, GEMM_SMEM>>>(
            p_ab, pw, pb, p_h, nullptr, C, C, OUT_F32);
        resid_sa_kernel<<<(NQ + 255) / 256, 256>>>(xo, p_h, p_ada, shift);
        ln_mod_kernel<<<MROWS, 128>>>(xo, p_ada, p_ab, 0, 0, 1536, 1152);
        gemm_bf16<<<dim3(FF / 128, MROWS / 128), 256, GEMM_SMEM>>>(
            p_ab, f1w, f1b, nullptr, p_fb, FF, C, OUT_GELU_BF16);
        gemm_bf16<<<dim3(C / 128, MROWS / 128), 256, GEMM_SMEM>>>(
            p_fb, f2w, f2b, p_h, nullptr, C, FF, OUT_F32);
        resid_ff_kernel<<<(NQ + 255) / 256, 256>>>(xo, p_h, p_ada);
    }
}